// round 2
// baseline (speedup 1.0000x reference)
#include <cuda_runtime.h>
#include <math.h>

#define HH 1024
#define WW 1024
#define NPIX (HH * WW)
#define N_ITERS 100

#define TX 64          // tile width  (output pixels per block, x)
#define TY 16          // tile height
#define BT 512         // threads per block (32 x 16)

// ---------------- device scratch (statically allocated, ~60 MB) ----------------
__device__ float  g_w[8][NPIX];     // propagation weights, planar
__device__ float2 g_b[NPIX];        // source term (IQ at colored pixels, else 0)
__device__ float  g_Y[NPIX];        // luminance plane
__device__ unsigned char g_mask[NPIX];
__device__ float2 g_x0[NPIX];       // ping
__device__ float2 g_x1[NPIX];       // pong

// ---------------- setup: Y, IQ, isColored, b, x0 init ----------------
__global__ void setup_kernel(const float* __restrict__ gray,
                             const float* __restrict__ app) {
    int pix = blockIdx.x * blockDim.x + threadIdx.x;
    if (pix >= NPIX) return;
    float g0 = gray[3*pix+0], g1 = gray[3*pix+1], g2 = gray[3*pix+2];
    float a0 = app [3*pix+0], a1 = app [3*pix+1], a2 = app [3*pix+2];

    const float inv255 = 1.0f / 255.0f;
    float diff = (fabsf(g0-a0) + fabsf(g1-a1) + fabsf(g2-a2)) * inv255;
    bool colored = diff > 0.01f;

    float Y = (0.3f*g0 + 0.59f*g1 + 0.11f*g2) * inv255;

    float ya = (0.3f*a0 + 0.59f*a1 + 0.11f*a2) * inv255;
    float r  = a0 * inv255;
    float bl = a2 * inv255;
    float I = 0.74f*(r - ya) - 0.27f*(bl - ya);
    float Q = 0.48f*(r - ya) + 0.41f*(bl - ya);

    float2 b = colored ? make_float2(I, Q) : make_float2(0.0f, 0.0f);

    g_Y[pix]    = Y;
    g_b[pix]    = b;
    g_x0[pix]   = b;
    g_mask[pix] = colored ? 1 : 0;
}

// ---------------- weights: per-pixel 8-neighbor affinity ----------------
__global__ void weights_kernel() {
    int pix = blockIdx.x * blockDim.x + threadIdx.x;
    if (pix >= NPIX) return;
    int i = pix / WW, j = pix % WW;

    const int di[8] = {-1,-1,-1, 0, 0, 1, 1, 1};
    const int dj[8] = {-1, 0, 1,-1, 1,-1, 0, 1};

    float Y = g_Y[pix];
    float nbr[8], valid[8];
    #pragma unroll
    for (int k = 0; k < 8; k++) {
        int ii = i + di[k], jj = j + dj[k];
        bool in = (ii >= 0) & (ii < HH) & (jj >= 0) & (jj < WW);
        valid[k] = in ? 1.0f : 0.0f;
        nbr[k]   = in ? g_Y[ii*WW + jj] : 0.0f;
    }

    float count = 1.0f, s = Y;
    #pragma unroll
    for (int k = 0; k < 8; k++) { count += valid[k]; s += nbr[k] * valid[k]; }
    float mean = s / count;

    float var = (Y - mean) * (Y - mean);
    #pragma unroll
    for (int k = 0; k < 8; k++) {
        float d = nbr[k] - mean;
        var += d * d * valid[k];
    }
    var /= count;
    float vs = fmaxf(0.6f * var, 2e-6f);
    float inv_vs = 1.0f / vs;

    float w[8], wsum = 0.0f;
    #pragma unroll
    for (int k = 0; k < 8; k++) {
        float d = nbr[k] - Y;
        w[k] = expf(-d * d * inv_vs) * valid[k];
        wsum += w[k];
    }
    float scale = (g_mask[pix] ? 0.0f : 1.0f) / wsum;
    #pragma unroll
    for (int k = 0; k < 8; k++) g_w[k][pix] = w[k] * scale;
}

// ---------------- fused 2-step stencil ----------------
// Per launch: x_out = Step(Step(x_in)). Weights/b for each thread's own pixels
// live in registers across both steps; intermediate lives in smem; only the
// 1-pixel halo ring of step-1 values needs extra w/b loads.
__global__ void __launch_bounds__(BT)
iter2_kernel(int src_is_x0) {
    __shared__ float2 sx[TY+4][TX+4];   // input x, halo 2  (20 x 68)
    __shared__ float2 sy[TY+2][TX+2];   // step-1 result, halo 1 (18 x 66)

    const float2* __restrict__ xin  = src_is_x0 ? g_x0 : g_x1;
    float2*       __restrict__ xout = src_is_x0 ? g_x1 : g_x0;

    const int di[8] = {-1,-1,-1, 0, 0, 1, 1, 1};
    const int dj[8] = {-1, 0, 1,-1, 1,-1, 0, 1};

    int tx = threadIdx.x;           // 0..31
    int ty = threadIdx.y;           // 0..15
    int tid = ty * 32 + tx;
    int bi0 = blockIdx.y * TY;
    int bj0 = blockIdx.x * TX;

    // ---- load input tile with halo 2 (clamped; garbage is weight-0) ----
    for (int idx = tid; idx < (TY+4)*(TX+4); idx += BT) {
        int r = idx / (TX+4), c = idx % (TX+4);
        int gi = min(max(bi0 - 2 + r, 0), HH-1);
        int gj = min(max(bj0 - 2 + c, 0), WW-1);
        sx[r][c] = xin[gi*WW + gj];
    }

    // ---- own-pixel invariants into registers (two pixels: tx and tx+32) ----
    int gi  = bi0 + ty;
    int pa  = gi * WW + (bj0 + tx);
    int pb  = pa + 32;
    float wa[8], wb[8];
    #pragma unroll
    for (int k = 0; k < 8; k++) { wa[k] = g_w[k][pa]; wb[k] = g_w[k][pb]; }
    float2 ba = g_b[pa];
    float2 bb = g_b[pb];

    __syncthreads();

    // ---- step 1: interior (own pixels) ----
    {
        float2 acc = ba;
        #pragma unroll
        for (int k = 0; k < 8; k++) {
            float2 t = sx[ty+2+di[k]][tx+2+dj[k]];
            acc.x = fmaf(wa[k], t.x, acc.x);
            acc.y = fmaf(wa[k], t.y, acc.y);
        }
        sy[ty+1][tx+1] = acc;
    }
    {
        float2 acc = bb;
        #pragma unroll
        for (int k = 0; k < 8; k++) {
            float2 t = sx[ty+2+di[k]][tx+34+dj[k]];
            acc.x = fmaf(wb[k], t.x, acc.x);
            acc.y = fmaf(wb[k], t.y, acc.y);
        }
        sy[ty+1][tx+33] = acc;
    }

    // ---- step 1: halo ring (164 pixels of the 66x18 region) ----
    if (tid < 2*(TX+2) + 2*TY) {
        int ry, rx;
        if (tid < TX+2)            { ry = 0;                 rx = tid; }
        else if (tid < 2*(TX+2))   { ry = TY+1;              rx = tid - (TX+2); }
        else if (tid < 2*(TX+2)+TY){ ry = 1 + tid - 2*(TX+2); rx = 0; }
        else                       { ry = 1 + tid - (2*(TX+2)+TY); rx = TX+1; }
        int hgi = min(max(bi0 - 1 + ry, 0), HH-1);
        int hgj = min(max(bj0 - 1 + rx, 0), WW-1);
        int p   = hgi * WW + hgj;
        float2 acc = g_b[p];
        #pragma unroll
        for (int k = 0; k < 8; k++) {
            float wk = g_w[k][p];
            float2 t = sx[ry+1+di[k]][rx+1+dj[k]];
            acc.x = fmaf(wk, t.x, acc.x);
            acc.y = fmaf(wk, t.y, acc.y);
        }
        sy[ry][rx] = acc;
    }

    __syncthreads();

    // ---- step 2: own pixels, weights/b already in registers ----
    {
        float2 acc = ba;
        #pragma unroll
        for (int k = 0; k < 8; k++) {
            float2 t = sy[ty+1+di[k]][tx+1+dj[k]];
            acc.x = fmaf(wa[k], t.x, acc.x);
            acc.y = fmaf(wa[k], t.y, acc.y);
        }
        xout[pa] = acc;
    }
    {
        float2 acc = bb;
        #pragma unroll
        for (int k = 0; k < 8; k++) {
            float2 t = sy[ty+1+di[k]][tx+33+dj[k]];
            acc.x = fmaf(wb[k], t.x, acc.x);
            acc.y = fmaf(wb[k], t.y, acc.y);
        }
        xout[pb] = acc;
    }
}

// ---------------- finalize: YIQ -> RGB ----------------
__global__ void final_kernel(float* __restrict__ out, int src_is_x0) {
    int pix = blockIdx.x * blockDim.x + threadIdx.x;
    if (pix >= NPIX) return;
    const float2* __restrict__ x = src_is_x0 ? g_x0 : g_x1;
    float y = g_Y[pix];
    float I = x[pix].x, Q = x[pix].y;

    float r = y + 0.9468822170900693f  * I + 0.6235565819861433f * Q;
    float g = y - 0.27478764629897834f * I - 0.6356910791873801f * Q;
    float b = y - 1.1085450346420322f  * I + 1.7090069284064666f * Q;

    out[3*pix+0] = fminf(fmaxf(r, 0.0f), 1.0f) * 255.0f;
    out[3*pix+1] = fminf(fmaxf(g, 0.0f), 1.0f) * 255.0f;
    out[3*pix+2] = fminf(fmaxf(b, 0.0f), 1.0f) * 255.0f;
}

extern "C" void kernel_launch(void* const* d_in, const int* in_sizes, int n_in,
                              void* d_out, int out_size) {
    const float* gray = (const float*)d_in[0];
    const float* app  = (const float*)d_in[1];
    float* out = (float*)d_out;

    int threads = 256;
    int blocks1d = (NPIX + threads - 1) / threads;

    setup_kernel<<<blocks1d, threads>>>(gray, app);
    weights_kernel<<<blocks1d, threads>>>();

    dim3 blk(32, TY);
    dim3 grd(WW / TX, HH / TY);
    int src_is_x0 = 1;
    for (int it = 0; it < N_ITERS / 2; it++) {   // 50 fused double-steps
        iter2_kernel<<<grd, blk>>>(src_is_x0);
        src_is_x0 ^= 1;
    }
    // 50 launches (even): final field back in g_x0 (src_is_x0 == 1)
    final_kernel<<<blocks1d, threads>>>(out, src_is_x0);
}

// round 7
// speedup vs baseline: 1.2431x; 1.2431x over previous
#include <cuda_runtime.h>
#include <math.h>

#define HH 1024
#define WW 1024
#define NPIX (HH * WW)
#define N_ITERS 100

// ---------------- device scratch (statically allocated, ~36 MB) ----------------
__device__ uint4  g_wq[NPIX];       // 8x unorm16 weights per pixel (16B)
__device__ float  g_Y[NPIX];        // luminance plane
__device__ unsigned char g_mask[NPIX];
__device__ float2 g_x0[NPIX];       // ping
__device__ float2 g_x1[NPIX];       // pong

// ---------------- setup: Y, IQ, isColored, x0 init ----------------
__global__ void setup_kernel(const float* __restrict__ gray,
                             const float* __restrict__ app) {
    int pix = blockIdx.x * blockDim.x + threadIdx.x;
    if (pix >= NPIX) return;
    float g0 = gray[3*pix+0], g1 = gray[3*pix+1], g2 = gray[3*pix+2];
    float a0 = app [3*pix+0], a1 = app [3*pix+1], a2 = app [3*pix+2];

    const float inv255 = 1.0f / 255.0f;
    float diff = (fabsf(g0-a0) + fabsf(g1-a1) + fabsf(g2-a2)) * inv255;
    bool colored = diff > 0.01f;

    float Y = (0.3f*g0 + 0.59f*g1 + 0.11f*g2) * inv255;

    float ya = (0.3f*a0 + 0.59f*a1 + 0.11f*a2) * inv255;
    float r  = a0 * inv255;
    float bl = a2 * inv255;
    float I = 0.74f*(r - ya) - 0.27f*(bl - ya);
    float Q = 0.48f*(r - ya) + 0.41f*(bl - ya);

    g_Y[pix]    = Y;
    g_x0[pix]   = colored ? make_float2(I, Q) : make_float2(0.0f, 0.0f);
    g_mask[pix] = colored ? 1 : 0;
}

// ---------------- weights: per-pixel 8-neighbor affinity, quantized unorm16 ----
__global__ void weights_kernel() {
    int pix = blockIdx.x * blockDim.x + threadIdx.x;
    if (pix >= NPIX) return;
    int i = pix / WW, j = pix % WW;

    const int di[8] = {-1,-1,-1, 0, 0, 1, 1, 1};
    const int dj[8] = {-1, 0, 1,-1, 1,-1, 0, 1};

    float Y = g_Y[pix];
    float nbr[8], valid[8];
    #pragma unroll
    for (int k = 0; k < 8; k++) {
        int ii = i + di[k], jj = j + dj[k];
        bool in = (ii >= 0) & (ii < HH) & (jj >= 0) & (jj < WW);
        valid[k] = in ? 1.0f : 0.0f;
        nbr[k]   = in ? g_Y[ii*WW + jj] : 0.0f;
    }

    float count = 1.0f, s = Y;
    #pragma unroll
    for (int k = 0; k < 8; k++) { count += valid[k]; s += nbr[k] * valid[k]; }
    float mean = s / count;

    float var = (Y - mean) * (Y - mean);
    #pragma unroll
    for (int k = 0; k < 8; k++) {
        float d = nbr[k] - mean;
        var += d * d * valid[k];
    }
    var /= count;
    float vs = fmaxf(0.6f * var, 2e-6f);
    float inv_vs = 1.0f / vs;

    float w[8], wsum = 0.0f;
    #pragma unroll
    for (int k = 0; k < 8; k++) {
        float d = nbr[k] - Y;
        w[k] = expf(-d * d * inv_vs) * valid[k];
        wsum += w[k];
    }
    // colored pixels: all weights 0 (the all-zero pattern encodes "colored")
    float scale = (g_mask[pix] ? 0.0f : 1.0f) / wsum * 65535.0f;

    unsigned int u[8];
    #pragma unroll
    for (int k = 0; k < 8; k++) u[k] = (unsigned int)rintf(w[k] * scale);

    uint4 q;
    q.x = u[0] | (u[1] << 16);
    q.y = u[2] | (u[3] << 16);
    q.z = u[4] | (u[5] << 16);
    q.w = u[6] | (u[7] << 16);
    g_wq[pix] = q;
}

// ---------------- main stencil iteration ----------------
__global__ void __launch_bounds__(256)
iter_kernel(int src_is_x0) {
    int j = blockIdx.x * 32 + threadIdx.x;
    int i = blockIdx.y * 8  + threadIdx.y;
    int pix = i * WW + j;

    const float2* __restrict__ xin  = src_is_x0 ? g_x0 : g_x1;
    float2*       __restrict__ xout = src_is_x0 ? g_x1 : g_x0;

    // clamped indices: border weights are exactly 0, clamped reads are inert
    int im = (i > 0)      ? i - 1 : 0;
    int ip = (i < HH - 1) ? i + 1 : HH - 1;
    int jm = (j > 0)      ? j - 1 : 0;
    int jp = (j < WW - 1) ? j + 1 : WW - 1;

    const float2* rm = xin + im * WW;
    const float2* r0 = xin + i  * WW;
    const float2* rp = xin + ip * WW;

    uint4 q = g_wq[pix];
    const float S = 1.0f / 65535.0f;
    float w0 = (float)(q.x & 0xFFFFu) * S;
    float w1 = (float)(q.x >> 16)     * S;
    float w2 = (float)(q.y & 0xFFFFu) * S;
    float w3 = (float)(q.y >> 16)     * S;
    float w4 = (float)(q.z & 0xFFFFu) * S;
    float w5 = (float)(q.z >> 16)     * S;
    float w6 = (float)(q.w & 0xFFFFu) * S;
    float w7 = (float)(q.w >> 16)     * S;
    // all-zero weights <=> colored pixel: pass center through unchanged
    float c = ((q.x | q.y | q.z | q.w) == 0u) ? 1.0f : 0.0f;

    float2 ctr = r0[j];
    float2 acc = make_float2(c * ctr.x, c * ctr.y);
    float2 t;
    t = rm[jm]; acc.x = fmaf(w0, t.x, acc.x); acc.y = fmaf(w0, t.y, acc.y);
    t = rm[j ]; acc.x = fmaf(w1, t.x, acc.x); acc.y = fmaf(w1, t.y, acc.y);
    t = rm[jp]; acc.x = fmaf(w2, t.x, acc.x); acc.y = fmaf(w2, t.y, acc.y);
    t = r0[jm]; acc.x = fmaf(w3, t.x, acc.x); acc.y = fmaf(w3, t.y, acc.y);
    t = r0[jp]; acc.x = fmaf(w4, t.x, acc.x); acc.y = fmaf(w4, t.y, acc.y);
    t = rp[jm]; acc.x = fmaf(w5, t.x, acc.x); acc.y = fmaf(w5, t.y, acc.y);
    t = rp[j ]; acc.x = fmaf(w6, t.x, acc.x); acc.y = fmaf(w6, t.y, acc.y);
    t = rp[jp]; acc.x = fmaf(w7, t.x, acc.x); acc.y = fmaf(w7, t.y, acc.y);

    xout[pix] = acc;
}

// ---------------- finalize: YIQ -> RGB ----------------
__global__ void final_kernel(float* __restrict__ out, int src_is_x0) {
    int pix = blockIdx.x * blockDim.x + threadIdx.x;
    if (pix >= NPIX) return;
    const float2* __restrict__ x = src_is_x0 ? g_x0 : g_x1;
    float y = g_Y[pix];
    float I = x[pix].x, Q = x[pix].y;

    float r = y + 0.9468822170900693f  * I + 0.6235565819861433f * Q;
    float g = y - 0.27478764629897834f * I - 0.6356910791873801f * Q;
    float b = y - 1.1085450346420322f  * I + 1.7090069284064666f * Q;

    out[3*pix+0] = fminf(fmaxf(r, 0.0f), 1.0f) * 255.0f;
    out[3*pix+1] = fminf(fmaxf(g, 0.0f), 1.0f) * 255.0f;
    out[3*pix+2] = fminf(fmaxf(b, 0.0f), 1.0f) * 255.0f;
}

extern "C" void kernel_launch(void* const* d_in, const int* in_sizes, int n_in,
                              void* d_out, int out_size) {
    const float* gray = (const float*)d_in[0];
    const float* app  = (const float*)d_in[1];
    float* out = (float*)d_out;

    int threads = 256;
    int blocks1d = (NPIX + threads - 1) / threads;

    setup_kernel<<<blocks1d, threads>>>(gray, app);
    weights_kernel<<<blocks1d, threads>>>();

    dim3 blk(32, 8);
    dim3 grd(WW / 32, HH / 8);
    int src_is_x0 = 1;
    for (int it = 0; it < N_ITERS; it++) {
        iter_kernel<<<grd, blk>>>(src_is_x0);
        src_is_x0 ^= 1;
    }
    // 100 launches (even): final field back in g_x0 (src_is_x0 == 1)
    final_kernel<<<blocks1d, threads>>>(out, src_is_x0);
}